// round 14
// baseline (speedup 1.0000x reference)
#include <cuda_runtime.h>
#include <cuda_bf16.h>
#include <math_constants.h>
#include <cstdint>

#define BATCH 16384
#define NN    50
#define ROWS  (BATCH * NN)        // 819200 = 6400 * 128 exactly
#define LDSP  40                  // padded smem row stride in halves (80B)

typedef unsigned int       u32;
typedef unsigned short     u16;
typedef unsigned long long u64;

// ---------------------------------------------------------------------------
// Static device scratch (no allocations allowed)
// ---------------------------------------------------------------------------
__device__ unsigned char g_mask_user[ROWS];
__device__ unsigned char g_mask_news[ROWS];
__device__ int g_mask_mode;  // 0=uint8, 1=int32, 2=float32
__device__ u16 g_Whi_u[128 * 128], g_Wlo_u[128 * 128];   // [H][Din] bf16 bits
__device__ u16 g_Whi_n[128 * 128], g_Wlo_n[128 * 128];
__device__ u16 g_Whi_s[128 * 384], g_Wlo_s[128 * 384];
__device__ float g_S_u[ROWS], g_S_n[ROWS], g_S_s[ROWS];  // raw scores

// ---------------------------------------------------------------------------
// Mask dtype sniffing (proven): scan first 64KB as u32 words.
// ---------------------------------------------------------------------------
__global__ void detect_mask_kernel(const unsigned int* __restrict__ w) {
    __shared__ int fF, fU;
    if (threadIdx.x == 0) { fF = 0; fU = 0; }
    __syncthreads();
    int lf = 0, lu = 0;
    for (int i = threadIdx.x; i < 16384; i += 256) {
        unsigned v = w[i];
        if (v == 0x3F800000u) lf = 1;
        else if (v != 0u && v != 1u) lu = 1;
    }
    if (lf) atomicOr(&fF, 1);
    if (lu) atomicOr(&fU, 1);
    __syncthreads();
    if (threadIdx.x == 0) g_mask_mode = fF ? 2 : (fU ? 0 : 1);
}

__global__ void expand_mask_kernel(const void* __restrict__ src,
                                   unsigned char* __restrict__ dst, int n) {
    int i = blockIdx.x * blockDim.x + threadIdx.x;
    if (i >= n) return;
    int m = g_mask_mode;
    unsigned char v;
    if (m == 0)      v = (((const unsigned char*)src)[i] != 0);
    else if (m == 1) v = (((const int*)src)[i] != 0);
    else             v = (((const float*)src)[i] != 0.0f);
    dst[i] = v;
}

// ---------------------------------------------------------------------------
// Split W into bf16 hi/lo, keeping [H][Din] row-major (mma .col B layout).
// ---------------------------------------------------------------------------
__global__ void prep_w_kernel(const float* __restrict__ Wu,
                              const float* __restrict__ Wn,
                              const float* __restrict__ Ws) {
    int i = blockIdx.x * blockDim.x + threadIdx.x;
    const float* src; u16 *hi, *lo; int off;
    if (i < 16384)      { src = Wu; hi = g_Whi_u; lo = g_Wlo_u; off = i; }
    else if (i < 32768) { src = Wn; hi = g_Whi_n; lo = g_Wlo_n; off = i - 16384; }
    else if (i < 81920) { src = Ws; hi = g_Whi_s; lo = g_Wlo_s; off = i - 32768; }
    else return;
    float v = src[off];
    __nv_bfloat16 h = __float2bfloat16(v);
    __nv_bfloat16 l = __float2bfloat16(v - __bfloat162float(h));
    hi[off] = *reinterpret_cast<u16*>(&h);
    lo[off] = *reinterpret_cast<u16*>(&l);
}

// ---------------------------------------------------------------------------
// Warp MMA / async-copy helpers
// ---------------------------------------------------------------------------
__device__ __forceinline__ void ldm4(u32& r0, u32& r1, u32& r2, u32& r3, u32 addr) {
    asm volatile("ldmatrix.sync.aligned.m8n8.x4.shared.b16 {%0,%1,%2,%3}, [%4];"
                 : "=r"(r0), "=r"(r1), "=r"(r2), "=r"(r3) : "r"(addr));
}
__device__ __forceinline__ void hmma(float* c, const u32* a, const u32* b) {
    asm volatile("mma.sync.aligned.m16n8k16.row.col.f32.bf16.bf16.f32 "
                 "{%0,%1,%2,%3}, {%4,%5,%6,%7}, {%8,%9}, {%0,%1,%2,%3};"
                 : "+f"(c[0]), "+f"(c[1]), "+f"(c[2]), "+f"(c[3])
                 : "r"(a[0]), "r"(a[1]), "r"(a[2]), "r"(a[3]),
                   "r"(b[0]), "r"(b[1]));
}
__device__ __forceinline__ void cp16(u32 daddr, const void* gaddr) {
    asm volatile("cp.async.ca.shared.global [%0], [%1], 16;"
                 :: "r"(daddr), "l"(gaddr));
}
#define CP_COMMIT() asm volatile("cp.async.commit_group;" ::: "memory")
#define CP_WAIT0()  asm volatile("cp.async.wait_group 0;" ::: "memory")

// Fast tanh: 1 - 2/(exp(2x)+1). MUFU-based; abs err ~1e-7 (gate is 1e-3).
__device__ __forceinline__ float tanh_fast(float x) {
    float e = __expf(2.0f * x);
    return 1.0f - 2.0f / (e + 1.0f);
}

__device__ __forceinline__ u32 bits2(__nv_bfloat162 v) {
    return *reinterpret_cast<u32*>(&v);
}

// ---------------------------------------------------------------------------
// Tensor-core GEMM + fused score kernel (v2).
//   Z = X (ROWS x D) * W^T, 3-term bf16 split, fp32 acc.
//   CTA tile 128x128, 128 threads = 4 warps (2m x 2n), warp tile 64x64.
//   Double-buffered smem K-chunks of 32; B staged via cp.async (pre-split W),
//   A loaded to regs + converted under the MMA shadow. Term-major HMMA order
//   (8 independent MMAs between accumulator reuse).
// ---------------------------------------------------------------------------
template <int D>
__global__ void __launch_bounds__(128, 2)
gemm_score_kernel(const float* __restrict__ x,
                  const u16* __restrict__ Whi,
                  const u16* __restrict__ Wlo,
                  const float* __restrict__ bias,
                  const float* __restrict__ uvec,
                  const float* __restrict__ qvec,
                  float* __restrict__ sraw) {
    extern __shared__ char smp[];
    u16* pAh[2] = { (u16*)(smp),         (u16*)(smp + 10240) };
    u16* pAl[2] = { (u16*)(smp + 20480), (u16*)(smp + 30720) };
    u16* pBh[2] = { (u16*)(smp + 40960), (u16*)(smp + 51200) };
    u16* pBl[2] = { (u16*)(smp + 61440), (u16*)(smp + 71680) };
    float* sq  = (float*)(smp + 81920);
    float* sbu = (float*)(smp + 82432);
    float (*sred)[2] = (float (*)[2])(smp + 82944);

    const int tid = threadIdx.x;
    const int lane = tid & 31, wid = tid >> 5;
    const int wm = wid >> 1, wn = wid & 1;            // 2 x 2 warp grid
    const size_t r0 = (size_t)blockIdx.x * 128;

    sq[tid]  = qvec[tid];
    sbu[tid] = bias[tid] + uvec[tid];

    // ldmatrix per-lane byte offsets (80B padded rows -> conflict-free; proven)
    const u32 offA = ((lane & 7) + 8 * ((lane >> 3) & 1)) * (LDSP * 2)
                   + (lane >> 4) * 16;
    const u32 offB = ((lane & 7) + 8 * (lane >> 4)) * (LDSP * 2)
                   + ((lane >> 3) & 1) * 16;

    float acc[4][8][4];
    #pragma unroll
    for (int i = 0; i < 4; ++i)
        #pragma unroll
        for (int j = 0; j < 8; ++j)
            #pragma unroll
            for (int r = 0; r < 4; ++r) acc[i][j][r] = 0.0f;

    // Per-thread staging: A row = tid (32 floats/chunk), B row = tid (32 halves)
    const float* Ag  = x + (r0 + tid) * D;
    const u16* BgH = Whi + (size_t)tid * D;
    const u16* BgL = Wlo + (size_t)tid * D;

    float4 areg[8];

    // --- helpers as lambdas ---
    auto ldA = [&](int kc) {
        #pragma unroll
        for (int j = 0; j < 8; ++j)
            areg[j] = *(const float4*)(Ag + kc * 32 + j * 4);
    };
    auto stsA = [&](int buf) {
        u16* dh = pAh[buf] + tid * LDSP;
        u16* dl = pAl[buf] + tid * LDSP;
        #pragma unroll
        for (int j = 0; j < 8; ++j) {
            float4 v = areg[j];
            __nv_bfloat162 h01 = __float22bfloat162_rn(make_float2(v.x, v.y));
            __nv_bfloat162 h23 = __float22bfloat162_rn(make_float2(v.z, v.w));
            float2 f01 = __bfloat1622float2(h01);
            float2 f23 = __bfloat1622float2(h23);
            __nv_bfloat162 l01 = __float22bfloat162_rn(make_float2(v.x - f01.x, v.y - f01.y));
            __nv_bfloat162 l23 = __float22bfloat162_rn(make_float2(v.z - f23.x, v.w - f23.y));
            *(uint2*)(dh + j * 4) = make_uint2(bits2(h01), bits2(h23));
            *(uint2*)(dl + j * 4) = make_uint2(bits2(l01), bits2(l23));
        }
    };
    auto cpB = [&](int kc, int buf) {
        u32 dh = (u32)__cvta_generic_to_shared(pBh[buf] + tid * LDSP);
        u32 dl = (u32)__cvta_generic_to_shared(pBl[buf] + tid * LDSP);
        #pragma unroll
        for (int c = 0; c < 4; ++c) {
            cp16(dh + c * 16, BgH + kc * 32 + c * 8);
            cp16(dl + c * 16, BgL + kc * 32 + c * 8);
        }
        CP_COMMIT();
    };

    // ---- prologue: stage chunk 0 ----
    ldA(0);
    cpB(0, 0);
    stsA(0);
    CP_WAIT0();
    __syncthreads();

    const int NC = D / 32;
    for (int kc = 0; kc < NC; ++kc) {
        const int cur = kc & 1, nxt = cur ^ 1;
        const bool hn = (kc + 1 < NC);
        if (hn) { ldA(kc + 1); cpB(kc + 1, nxt); }   // fire loads; MMA hides them

        const u32 aHb = (u32)__cvta_generic_to_shared(pAh[cur]);
        const u32 aLb = (u32)__cvta_generic_to_shared(pAl[cur]);
        const u32 bHb = (u32)__cvta_generic_to_shared(pBh[cur]);
        const u32 bLb = (u32)__cvta_generic_to_shared(pBl[cur]);

        #pragma unroll
        for (int s = 0; s < 2; ++s) {
            u32 Ah[4][4], Al[4][4];
            #pragma unroll
            for (int mt = 0; mt < 4; ++mt) {
                u32 ad = (u32)(wm * 64 + mt * 16) * (LDSP * 2) + s * 32;
                ldm4(Ah[mt][0], Ah[mt][1], Ah[mt][2], Ah[mt][3], aHb + ad + offA);
                ldm4(Al[mt][0], Al[mt][1], Al[mt][2], Al[mt][3], aLb + ad + offA);
            }
            #pragma unroll
            for (int pr = 0; pr < 4; ++pr) {
                u32 Bh[4], Bl[4];
                u32 bd = (u32)(wn * 64 + pr * 16) * (LDSP * 2) + s * 32;
                ldm4(Bh[0], Bh[1], Bh[2], Bh[3], bHb + bd + offB);
                ldm4(Bl[0], Bl[1], Bl[2], Bl[3], bLb + bd + offB);
                // term-major: 8 independent HMMAs between accumulator reuse
                #pragma unroll
                for (int mt = 0; mt < 4; ++mt) {
                    hmma(acc[mt][2 * pr],     Ah[mt], &Bh[0]);
                    hmma(acc[mt][2 * pr + 1], Ah[mt], &Bh[2]);
                }
                #pragma unroll
                for (int mt = 0; mt < 4; ++mt) {
                    hmma(acc[mt][2 * pr],     Ah[mt], &Bl[0]);
                    hmma(acc[mt][2 * pr + 1], Ah[mt], &Bl[2]);
                }
                #pragma unroll
                for (int mt = 0; mt < 4; ++mt) {
                    hmma(acc[mt][2 * pr],     Al[mt], &Bh[0]);
                    hmma(acc[mt][2 * pr + 1], Al[mt], &Bh[2]);
                }
            }
        }
        if (hn) { stsA(nxt); CP_WAIT0(); }
        __syncthreads();
    }

    // ---- fused score epilogue ----
    // Thread owns rows wm*64 + mt*16 + (lane>>2) + half*8,
    //            cols wn*64 + nt*8 + 2*(lane&3) (+1).
    #pragma unroll
    for (int mt = 0; mt < 4; ++mt) {
        #pragma unroll
        for (int half = 0; half < 2; ++half) {
            float p = 0.0f;
            #pragma unroll
            for (int nt = 0; nt < 8; ++nt) {
                int h0 = wn * 64 + nt * 8 + 2 * (lane & 3);
                p += sq[h0]     * tanh_fast(acc[mt][nt][half * 2]     + sbu[h0]);
                p += sq[h0 + 1] * tanh_fast(acc[mt][nt][half * 2 + 1] + sbu[h0 + 1]);
            }
            p += __shfl_xor_sync(0xffffffffu, p, 1);
            p += __shfl_xor_sync(0xffffffffu, p, 2);
            if ((lane & 3) == 0)
                sred[wm * 64 + mt * 16 + (lane >> 2) + half * 8][wn] = p;
        }
    }
    __syncthreads();
    sraw[r0 + tid] = sred[tid][0] + sred[tid][1];
}

#define GEMM_SMEM 84992

// ---------------------------------------------------------------------------
// Masked softmax + weighted sum (proven). One CTA (128 threads) per batch row.
// ---------------------------------------------------------------------------
template <int D>
__global__ void __launch_bounds__(128)
softmax_out_kernel(const float* __restrict__ x,
                   const float* __restrict__ sraw,
                   const unsigned char* __restrict__ mask,
                   float* __restrict__ out) {
    __shared__ float attn[NN];
    const int t = threadIdx.x;
    const int b = blockIdx.x;

    if (t < 32) {
        const float* sb = sraw + (size_t)b * NN;
        const unsigned char* mb = mask + (size_t)b * NN;
        bool v0 = (mb[t] != 0);
        float a0 = v0 ? sb[t] : -CUDART_INF_F;
        bool v1 = false;
        float a1 = -CUDART_INF_F;
        if (t + 32 < NN) { v1 = (mb[t + 32] != 0); a1 = v1 ? sb[t + 32] : -CUDART_INF_F; }
        float mx = fmaxf(a0, a1);
        #pragma unroll
        for (int o = 16; o; o >>= 1)
            mx = fmaxf(mx, __shfl_xor_sync(0xffffffffu, mx, o));
        float e0 = v0 ? __expf(a0 - mx) : 0.0f;
        float e1 = v1 ? __expf(a1 - mx) : 0.0f;
        float su = e0 + e1;
        #pragma unroll
        for (int o = 16; o; o >>= 1)
            su += __shfl_xor_sync(0xffffffffu, su, o);
        float inv = 1.0f / su;
        attn[t] = e0 * inv;
        if (t + 32 < NN) attn[t + 32] = e1 * inv;
    }
    __syncthreads();

    const float* xb = x + (size_t)b * NN * D;
    const int NOUT = D / 128;
    float acc[NOUT];
    #pragma unroll
    for (int c = 0; c < NOUT; ++c) acc[c] = 0.0f;
    #pragma unroll 5
    for (int n = 0; n < NN; ++n) {
        float an = attn[n];
        #pragma unroll
        for (int c = 0; c < NOUT; ++c)
            acc[c] = fmaf(an, xb[(size_t)n * D + t + c * 128], acc[c]);
    }
    #pragma unroll
    for (int c = 0; c < NOUT; ++c)
        out[(size_t)b * D + t + c * 128] = acc[c];
}

// ---------------------------------------------------------------------------
// Launch. Inputs (metadata order):
//  0 users (B,N,128)  1 news (B,N,128)  2 sem (B,N,384)
//  3 user_mask (B,N)  4 news_mask (B,N)
//  5-8 W/b/u/q user   9-12 W/b/u/q news   13-16 W/b/u/q sem
// Output: [agg_users (B,128) | agg_news (B,128) | agg_sem (B,384)] f32
// ncu profiles launch slot 4 -> keep GEMM<384> there.
// ---------------------------------------------------------------------------
extern "C" void kernel_launch(void* const* d_in, const int* in_sizes, int n_in,
                              void* d_out, int out_size) {
    const float* users = (const float*)d_in[0];
    const float* news  = (const float*)d_in[1];
    const float* sem   = (const float*)d_in[2];
    const void*  mu    = d_in[3];
    const void*  mn    = d_in[4];
    const float* W_user = (const float*)d_in[5];
    const float* b_user = (const float*)d_in[6];
    const float* u_user = (const float*)d_in[7];
    const float* q_user = (const float*)d_in[8];
    const float* W_news = (const float*)d_in[9];
    const float* b_news = (const float*)d_in[10];
    const float* u_news = (const float*)d_in[11];
    const float* q_news = (const float*)d_in[12];
    const float* W_sem  = (const float*)d_in[13];
    const float* b_sem  = (const float*)d_in[14];
    const float* u_sem  = (const float*)d_in[15];
    const float* q_sem  = (const float*)d_in[16];
    float* out = (float*)d_out;

    void* p;
    cudaGetSymbolAddress(&p, g_mask_user); unsigned char* gmu = (unsigned char*)p;
    cudaGetSymbolAddress(&p, g_mask_news); unsigned char* gmn = (unsigned char*)p;
    cudaGetSymbolAddress(&p, g_Whi_u); u16* whu = (u16*)p;
    cudaGetSymbolAddress(&p, g_Wlo_u); u16* wlu = (u16*)p;
    cudaGetSymbolAddress(&p, g_Whi_n); u16* whn = (u16*)p;
    cudaGetSymbolAddress(&p, g_Wlo_n); u16* wln = (u16*)p;
    cudaGetSymbolAddress(&p, g_Whi_s); u16* whs = (u16*)p;
    cudaGetSymbolAddress(&p, g_Wlo_s); u16* wls = (u16*)p;
    cudaGetSymbolAddress(&p, g_S_u);  float* su = (float*)p;
    cudaGetSymbolAddress(&p, g_S_n);  float* sn = (float*)p;
    cudaGetSymbolAddress(&p, g_S_s);  float* ss = (float*)p;

    cudaFuncSetAttribute(gemm_score_kernel<128>,
                         cudaFuncAttributeMaxDynamicSharedMemorySize, GEMM_SMEM);
    cudaFuncSetAttribute(gemm_score_kernel<384>,
                         cudaFuncAttributeMaxDynamicSharedMemorySize, GEMM_SMEM);

    const int NBLK = ROWS / 128;   // 6400 GEMM CTAs

    detect_mask_kernel<<<1, 256>>>((const unsigned int*)mu);                   // slot 1
    prep_w_kernel<<<(81920 + 255) / 256, 256>>>(W_user, W_news, W_sem);        // slot 2
    expand_mask_kernel<<<(ROWS + 255) / 256, 256>>>(mu, gmu, ROWS);            // slot 3

    gemm_score_kernel<384><<<NBLK, 128, GEMM_SMEM>>>(                          // slot 4 (ncu)
        sem, whs, wls, b_sem, u_sem, q_sem, ss);
    gemm_score_kernel<128><<<NBLK, 128, GEMM_SMEM>>>(                          // slot 5
        users, whu, wlu, b_user, u_user, q_user, su);
    gemm_score_kernel<128><<<NBLK, 128, GEMM_SMEM>>>(                          // slot 6
        news, whn, wln, b_news, u_news, q_news, sn);

    expand_mask_kernel<<<(ROWS + 255) / 256, 256>>>(mn, gmn, ROWS);            // slot 7

    softmax_out_kernel<128><<<BATCH, 128>>>(users, su, gmu, out);                       // 8
    softmax_out_kernel<128><<<BATCH, 128>>>(news,  sn, gmn, out + (size_t)BATCH * 128); // 9
    softmax_out_kernel<384><<<BATCH, 128>>>(sem,   ss, gmn, out + (size_t)BATCH * 256); // 10
}